// round 1
// baseline (speedup 1.0000x reference)
#include <cuda_runtime.h>

#define N_NODESC 50000
#define N_EDGESC 500000
#define N_RELC   8
#define DIMC     128
#define A_DIMC   64

// ---------------- scratch (device globals: no allocation allowed) ----------------
// g_proj layout: [t][n][d], t = side*8 + r  (side 0 = dst rows of relations, side 1 = src rows)
__device__ __align__(16) float g_proj[(size_t)16 * N_NODESC * DIMC];   // 409.6 MB
__device__ __align__(16) float g_q[(size_t)N_NODESC * DIMC];           // cols 0..63 = qd, 64..127 = qs
__device__ __align__(16) float g_hN[(size_t)N_NODESC * DIMC];
__device__ float g_ex[N_EDGESC];
__device__ float g_denom[N_NODESC];
__device__ __align__(16) float g_Wq[DIMC * DIMC];        // B for the attention GEMM: [d][a]
__device__ __align__(16) float g_WlT[2 * DIMC * DIMC];   // W_lin transposed: [k][o]

// ---------------- f32x2 packed-FMA helpers (sm_100+) ----------------
__device__ __forceinline__ unsigned long long pack2(float x) {
    unsigned long long r;
    asm("mov.b64 %0, {%1, %1};" : "=l"(r) : "f"(x));
    return r;
}
__device__ __forceinline__ void ffma2(unsigned long long& acc, unsigned long long a,
                                      unsigned long long b) {
    asm("fma.rn.f32x2 %0, %1, %2, %0;" : "+l"(acc) : "l"(a), "l"(b));
}
__device__ __forceinline__ float2 unpack2(unsigned long long v) {
    float2 r;
    asm("mov.b64 {%0, %1}, %2;" : "=f"(r.x), "=f"(r.y) : "l"(v));
    return r;
}

// ---------------- init ----------------
__global__ void k_zero() {
    size_t i = (size_t)blockIdx.x * blockDim.x + threadIdx.x;
    if (i < (size_t)N_NODESC * DIMC) g_hN[i] = 0.0f;
    if (i < N_NODESC) g_denom[i] = 0.0f;
}

// Repack W_a -> g_Wq[d][a] and W_lin -> g_WlT[k][o]
__global__ void k_prep(const float* __restrict__ W_a, const float* __restrict__ W_lin) {
    int i = blockIdx.x * blockDim.x + threadIdx.x;
    if (i < DIMC * DIMC) {
        int d = i >> 7, a = i & 127;
        g_Wq[i] = (a < A_DIMC) ? W_a[a * 256 + d] : W_a[(a - A_DIMC) * 256 + DIMC + d];
    }
    if (i < 2 * DIMC * DIMC) {
        int k = i >> 7, o = i & 127;
        g_WlT[i] = W_lin[o * 256 + k];
    }
}

// ---------------- 17-way GEMM: C[t] = h @ B[t],  M=50000, N=128, K=128 ----------------
// t<16: B = relations[r, side*128 : side*128+128, :] -> g_proj[t]
// t=16: B = g_Wq -> g_q
__global__ __launch_bounds__(256) void k_gemm17(const float* __restrict__ h,
                                                const float* __restrict__ relations) {
    const int t = blockIdx.y;
    const float* __restrict__ B;
    float* __restrict__ C;
    if (t < 16) {
        int side = t >> 3, r = t & 7;
        B = relations + ((size_t)(r * 256 + side * 128)) * DIMC;
        C = g_proj + (size_t)t * N_NODESC * DIMC;
    } else {
        B = g_Wq;
        C = g_q;
    }

    __shared__ float As[16][132];   // [k][m], padded
    __shared__ float Bs[16][128];   // [k][n]

    const int tid = threadIdx.x;
    const int m0 = blockIdx.x * 128;
    const int tr = tid >> 4;            // 0..15  (8 M-rows each)
    const int tc = tid & 15;            // 0..15  (8 N-cols each)
    const int a_row = tid >> 2;         // 0..63
    const int a_col = (tid & 3) << 2;   // 0,4,8,12
    const int b_row = tid >> 5;         // 0..7
    const int b_col = (tid & 31) << 2;  // 0..124

    unsigned long long acc[8][4];
#pragma unroll
    for (int i = 0; i < 8; i++)
#pragma unroll
        for (int j = 0; j < 4; j++) acc[i][j] = 0ull;

    for (int k0 = 0; k0 < DIMC; k0 += 16) {
#pragma unroll
        for (int half = 0; half < 2; half++) {
            int m = a_row + half * 64;
            float4 v = make_float4(0.f, 0.f, 0.f, 0.f);
            if (m0 + m < N_NODESC)
                v = *(const float4*)(h + (size_t)(m0 + m) * DIMC + k0 + a_col);
            As[a_col + 0][m] = v.x;
            As[a_col + 1][m] = v.y;
            As[a_col + 2][m] = v.z;
            As[a_col + 3][m] = v.w;
        }
#pragma unroll
        for (int half = 0; half < 2; half++) {
            int kk = b_row + half * 8;
            *(float4*)&Bs[kk][b_col] = *(const float4*)(B + (size_t)(k0 + kk) * DIMC + b_col);
        }
        __syncthreads();

#pragma unroll
        for (int k = 0; k < 16; k++) {
            float4 a0 = *(const float4*)&As[k][tr * 8];
            float4 a1 = *(const float4*)&As[k][tr * 8 + 4];
            unsigned long long ap[8];
            ap[0] = pack2(a0.x); ap[1] = pack2(a0.y); ap[2] = pack2(a0.z); ap[3] = pack2(a0.w);
            ap[4] = pack2(a1.x); ap[5] = pack2(a1.y); ap[6] = pack2(a1.z); ap[7] = pack2(a1.w);
            ulonglong2 bq0 = *(const ulonglong2*)&Bs[k][tc * 8];
            ulonglong2 bq1 = *(const ulonglong2*)&Bs[k][tc * 8 + 4];
            unsigned long long bp[4] = {bq0.x, bq0.y, bq1.x, bq1.y};
#pragma unroll
            for (int i = 0; i < 8; i++)
#pragma unroll
                for (int j = 0; j < 4; j++) ffma2(acc[i][j], ap[i], bp[j]);
        }
        __syncthreads();
    }

#pragma unroll
    for (int i = 0; i < 8; i++) {
        int m = m0 + tr * 8 + i;
        if (m < N_NODESC) {
            float* cp = C + (size_t)m * DIMC + tc * 8;
#pragma unroll
            for (int j = 0; j < 4; j++) {
                float2 p = unpack2(acc[i][j]);
                *(float2*)(cp + j * 2) = p;
            }
        }
    }
}

// ---------------- per-edge attention score + exp + denom atomic ----------------
// score small (|s| < ~5 for this data) so exp(s)/sum(exp(s)) == softmax without max-subtract.
__global__ void k_score(const int* __restrict__ src, const int* __restrict__ dst,
                        const float* __restrict__ rel_att, const float* __restrict__ b_a) {
    int e = blockIdx.x * 8 + threadIdx.y;
    int lane = threadIdx.x;
    int s = __ldg(&src[e]);
    int d = __ldg(&dst[e]);
    float2 qd = *(const float2*)&g_q[(size_t)d * DIMC + lane * 2];
    float2 qs = *(const float2*)&g_q[(size_t)s * DIMC + A_DIMC + lane * 2];
    float2 ba = *(const float2*)&b_a[lane * 2];
    float2 ra = *(const float2*)&rel_att[lane * 2];   // rel_attention[0]
    float x0 = qd.x + qs.x + ba.x;
    x0 = x0 > 0.f ? x0 : 0.01f * x0;
    float x1 = qd.y + qs.y + ba.y;
    x1 = x1 > 0.f ? x1 : 0.01f * x1;
    float p = ra.x * x0 + ra.y * x1;
#pragma unroll
    for (int o = 16; o > 0; o >>= 1) p += __shfl_xor_sync(0xffffffffu, p, o);
    if (lane == 0) {
        float ex = expf(p);
        g_ex[e] = ex;
        atomicAdd(&g_denom[d], ex);
    }
}

// ---------------- per-edge message: gate * attn * h[src], scatter-add into h_N[dst] ----------------
__global__ void k_msg(const float* __restrict__ h, const int* __restrict__ src,
                      const int* __restrict__ dst, const int* __restrict__ etype) {
    int e = blockIdx.x * 8 + threadIdx.y;
    int lane = threadIdx.x;
    int s = __ldg(&src[e]);
    int d = __ldg(&dst[e]);
    int r = __ldg(&etype[e]);
    float attn = __fdividef(g_ex[e], g_denom[d]);
    float4 pd = *(const float4*)&g_proj[((size_t)r * N_NODESC + d) * DIMC + lane * 4];
    float4 ps = *(const float4*)&g_proj[((size_t)(8 + r) * N_NODESC + s) * DIMC + lane * 4];
    float4 hs = *(const float4*)&h[(size_t)s * DIMC + lane * 4];
    float g0 = 1.0f / (1.0f + expf(-(pd.x + ps.x)));
    float g1 = 1.0f / (1.0f + expf(-(pd.y + ps.y)));
    float g2 = 1.0f / (1.0f + expf(-(pd.z + ps.z)));
    float g3 = 1.0f / (1.0f + expf(-(pd.w + ps.w)));
    float* o = &g_hN[(size_t)d * DIMC + lane * 4];
    atomicAdd(o + 0, hs.x * attn * g0);
    atomicAdd(o + 1, hs.y * attn * g1);
    atomicAdd(o + 2, hs.z * attn * g2);
    atomicAdd(o + 3, hs.w * attn * g3);
}

// ---------------- final: out = leaky([h ; h_N] @ W_lin^T + b_lin), K=256 ----------------
__global__ __launch_bounds__(256) void k_final(const float* __restrict__ h,
                                               const float* __restrict__ b_lin,
                                               float* __restrict__ out) {
    __shared__ float As[16][132];
    __shared__ float Bs[16][128];

    const int tid = threadIdx.x;
    const int m0 = blockIdx.x * 128;
    const int tr = tid >> 4;
    const int tc = tid & 15;
    const int a_row = tid >> 2;
    const int a_col = (tid & 3) << 2;
    const int b_row = tid >> 5;
    const int b_col = (tid & 31) << 2;

    unsigned long long acc[8][4];
#pragma unroll
    for (int i = 0; i < 8; i++)
#pragma unroll
        for (int j = 0; j < 4; j++) acc[i][j] = 0ull;

    for (int k0 = 0; k0 < 2 * DIMC; k0 += 16) {
        const float* Asrc = (k0 < DIMC) ? (h + k0) : (g_hN + (k0 - DIMC));
#pragma unroll
        for (int half = 0; half < 2; half++) {
            int m = a_row + half * 64;
            float4 v = make_float4(0.f, 0.f, 0.f, 0.f);
            if (m0 + m < N_NODESC)
                v = *(const float4*)(Asrc + (size_t)(m0 + m) * DIMC + a_col);
            As[a_col + 0][m] = v.x;
            As[a_col + 1][m] = v.y;
            As[a_col + 2][m] = v.z;
            As[a_col + 3][m] = v.w;
        }
#pragma unroll
        for (int half = 0; half < 2; half++) {
            int kk = b_row + half * 8;
            *(float4*)&Bs[kk][b_col] =
                *(const float4*)(g_WlT + (size_t)(k0 + kk) * DIMC + b_col);
        }
        __syncthreads();

#pragma unroll
        for (int k = 0; k < 16; k++) {
            float4 a0 = *(const float4*)&As[k][tr * 8];
            float4 a1 = *(const float4*)&As[k][tr * 8 + 4];
            unsigned long long ap[8];
            ap[0] = pack2(a0.x); ap[1] = pack2(a0.y); ap[2] = pack2(a0.z); ap[3] = pack2(a0.w);
            ap[4] = pack2(a1.x); ap[5] = pack2(a1.y); ap[6] = pack2(a1.z); ap[7] = pack2(a1.w);
            ulonglong2 bq0 = *(const ulonglong2*)&Bs[k][tc * 8];
            ulonglong2 bq1 = *(const ulonglong2*)&Bs[k][tc * 8 + 4];
            unsigned long long bp[4] = {bq0.x, bq0.y, bq1.x, bq1.y};
#pragma unroll
            for (int i = 0; i < 8; i++)
#pragma unroll
                for (int j = 0; j < 4; j++) ffma2(acc[i][j], ap[i], bp[j]);
        }
        __syncthreads();
    }

#pragma unroll
    for (int i = 0; i < 8; i++) {
        int m = m0 + tr * 8 + i;
        if (m < N_NODESC) {
            float* cp = out + (size_t)m * DIMC + tc * 8;
#pragma unroll
            for (int j = 0; j < 4; j++) {
                float2 p = unpack2(acc[i][j]);
                float2 bl = *(const float2*)&b_lin[tc * 8 + j * 2];
                float v0 = p.x + bl.x;
                float v1 = p.y + bl.y;
                v0 = v0 > 0.f ? v0 : 0.01f * v0;
                v1 = v1 > 0.f ? v1 : 0.01f * v1;
                *(float2*)(cp + j * 2) = make_float2(v0, v1);
            }
        }
    }
}

// ---------------- launch ----------------
extern "C" void kernel_launch(void* const* d_in, const int* in_sizes, int n_in,
                              void* d_out, int out_size) {
    const float* h      = (const float*)d_in[0];
    const float* rel    = (const float*)d_in[1];
    const float* relatt = (const float*)d_in[2];
    const float* W_a    = (const float*)d_in[3];
    const float* b_a    = (const float*)d_in[4];
    const float* W_lin  = (const float*)d_in[5];
    const float* b_lin  = (const float*)d_in[6];
    const int* src   = (const int*)d_in[7];
    const int* dst   = (const int*)d_in[8];
    const int* etype = (const int*)d_in[9];
    float* out = (float*)d_out;

    k_zero<<<(N_NODESC * DIMC + 1023) / 1024, 1024>>>();
    k_prep<<<(2 * DIMC * DIMC + 255) / 256, 256>>>(W_a, W_lin);

    dim3 gg((N_NODESC + 127) / 128, 17);
    k_gemm17<<<gg, 256>>>(h, rel);

    dim3 be(32, 8);
    k_score<<<N_EDGESC / 8, be>>>(src, dst, relatt, b_a);
    k_msg<<<N_EDGESC / 8, be>>>(h, src, dst, etype);

    k_final<<<(N_NODESC + 127) / 128, 256>>>(h, b_lin, out);
}

// round 4
// speedup vs baseline: 1.6893x; 1.6893x over previous
#include <cuda_runtime.h>
#include <cuda_bf16.h>
#include <cstdint>

#define N_NODESC 50000
#define N_EDGESC 500000
#define DIMC     128
#define A_DIMC   64
#define NPADC    50048      // 391 * 128
#define MBLKS    391
#define TCNT     17

// ---------------- device scratch (no allocation allowed) ----------------
__device__ __align__(16) __nv_bfloat16 g_hh[(size_t)NPADC * DIMC];     // h hi (bf16)
__device__ __align__(16) __nv_bfloat16 g_hl[(size_t)NPADC * DIMC];     // h lo (bf16)
__device__ __align__(16) __nv_bfloat16 g_Bh[(size_t)TCNT * DIMC * DIMC]; // [t][n][k]
__device__ __align__(16) __nv_bfloat16 g_Bl[(size_t)TCNT * DIMC * DIMC];
__device__ __align__(16) __nv_bfloat16 g_projb[(size_t)16 * N_NODESC * DIMC]; // 204.8MB
__device__ __align__(16) float g_q[(size_t)N_NODESC * DIMC];   // cols 0..63 qd, 64..127 qs
__device__ __align__(16) float g_hN[(size_t)N_NODESC * DIMC];
__device__ float g_ex[N_EDGESC];
__device__ float g_denom[N_NODESC];
__device__ __align__(16) float g_WlT[2 * DIMC * DIMC];

// ---------------- ptx helpers ----------------
__device__ __forceinline__ uint32_t smem_u32(const void* p) {
    uint32_t a;
    asm("{ .reg .u64 t; cvta.to.shared.u64 t, %1; cvt.u32.u64 %0, t; }" : "=r"(a) : "l"(p));
    return a;
}
__device__ __forceinline__ void cp16(uint32_t dst, const void* src) {
    asm volatile("cp.async.cg.shared.global [%0], [%1], 16;" :: "r"(dst), "l"(src));
}
#define CP_COMMIT() asm volatile("cp.async.commit_group;" ::: "memory")
#define CP_WAIT0()  asm volatile("cp.async.wait_group 0;" ::: "memory")

__device__ __forceinline__ void ldmx4(uint32_t* r, uint32_t addr) {
    asm volatile("ldmatrix.sync.aligned.m8n8.x4.shared.b16 {%0,%1,%2,%3}, [%4];"
                 : "=r"(r[0]), "=r"(r[1]), "=r"(r[2]), "=r"(r[3]) : "r"(addr));
}
__device__ __forceinline__ void mma16816(float* d, const uint32_t* a, uint32_t b0, uint32_t b1) {
    asm volatile("mma.sync.aligned.m16n8k16.row.col.f32.bf16.bf16.f32 "
                 "{%0,%1,%2,%3}, {%4,%5,%6,%7}, {%8,%9}, {%0,%1,%2,%3};"
                 : "+f"(d[0]), "+f"(d[1]), "+f"(d[2]), "+f"(d[3])
                 : "r"(a[0]), "r"(a[1]), "r"(a[2]), "r"(a[3]), "r"(b0), "r"(b1));
}

// ---------------- prep kernels ----------------
__global__ void k_zero() {
    size_t i = (size_t)blockIdx.x * blockDim.x + threadIdx.x;
    if (i < (size_t)N_NODESC * DIMC) g_hN[i] = 0.0f;
    if (i < N_NODESC) g_denom[i] = 0.0f;
}

__global__ void k_cvtA(const float* __restrict__ h) {
    int i = blockIdx.x * 256 + threadIdx.x;
    if (i < N_NODESC * DIMC) {
        float v = h[i];
        __nv_bfloat16 hi = __float2bfloat16(v);
        g_hh[i] = hi;
        g_hl[i] = __float2bfloat16(v - __bfloat162float(hi));
    }
}

__global__ void k_prepB(const float* __restrict__ rel, const float* __restrict__ W_a,
                        const float* __restrict__ W_lin) {
    int i = blockIdx.x * 256 + threadIdx.x;
    if (i < TCNT * DIMC * DIMC) {
        int t = i >> 14, n = (i >> 7) & 127, k = i & 127;
        float v;
        if (t < 16) {
            int side = t >> 3, r = t & 7;
            v = rel[((size_t)(r * 256 + side * 128 + k)) * 128 + n];
        } else {
            v = (n < A_DIMC) ? W_a[n * 256 + k] : W_a[(n - A_DIMC) * 256 + DIMC + k];
        }
        __nv_bfloat16 hi = __float2bfloat16(v);
        g_Bh[i] = hi;
        g_Bl[i] = __float2bfloat16(v - __bfloat162float(hi));
    }
    if (i < 2 * DIMC * DIMC) {
        int k = i >> 7, o = i & 127;
        g_WlT[i] = W_lin[o * 256 + k];
    }
}

// ---------------- 17-way GEMM on mma.sync (bf16 3-term split) ----------------
// grid (MBLKS, TCNT), 256 threads (8 warps, 4x2 -> warp tile 32x64).
// SMEM tiles padded to 136 halves/row (272B) for conflict-free ldmatrix.
#define ROWB 272
#define TILEB 34816           // 128 * 272
#define SM_TOTAL (4 * TILEB)  // Ah, Al, Bh, Bl

__global__ void __launch_bounds__(256, 1) k_tgemm() {
    extern __shared__ char smem[];
    const uint32_t sb = smem_u32(smem);
    const uint32_t sAh = sb, sAl = sb + TILEB, sBh = sb + 2 * TILEB, sBl = sb + 3 * TILEB;

    const int tid = threadIdx.x;
    const int lane = tid & 31;
    const int wid = tid >> 5;
    const int t = blockIdx.y;
    const int m0 = blockIdx.x * 128;

    // ---- load tiles: 128 rows x 16 chunks of 16B each (full 256B row) ----
    {
        const __nv_bfloat16* Ah = g_hh + (size_t)m0 * DIMC;
        const __nv_bfloat16* Al = g_hl + (size_t)m0 * DIMC;
        const __nv_bfloat16* Bh = g_Bh + (size_t)t * DIMC * DIMC;
        const __nv_bfloat16* Bl = g_Bl + (size_t)t * DIMC * DIMC;
        for (int idx = tid; idx < 2048; idx += 256) {
            int row = idx >> 4, c = idx & 15;
            uint32_t doff = row * ROWB + c * 16;
            size_t soff = (size_t)row * DIMC + c * 8;
            cp16(sAh + doff, Ah + soff);
            cp16(sAl + doff, Al + soff);
            cp16(sBh + doff, Bh + soff);
            cp16(sBl + doff, Bl + soff);
        }
    }
    CP_COMMIT();
    CP_WAIT0();
    __syncthreads();

    const int wm = wid & 3;          // m 32-block
    const int wn = wid >> 2;         // n 64-block
    const int mb = wm * 32;
    const int nb = wn * 64;

    // ldmatrix lane addressing
    const int a_row = (lane & 7) + 8 * ((lane >> 3) & 1);
    const int a_kh  = (lane >> 4) * 16;             // bytes
    const int b_row = (lane & 7) + 8 * (lane >> 4);
    const int b_kh  = ((lane >> 3) & 1) * 16;       // bytes

    float acc[2][8][4];
#pragma unroll
    for (int i = 0; i < 2; i++)
#pragma unroll
        for (int j = 0; j < 8; j++)
#pragma unroll
            for (int v = 0; v < 4; v++) acc[i][j][v] = 0.0f;

    for (int k0 = 0; k0 < 8; k0++) {
        const uint32_t kbyte = k0 * 32;
        uint32_t ah[2][4], al[2][4], bh[4][4], bl[4][4];
#pragma unroll
        for (int mt = 0; mt < 2; mt++) {
            uint32_t ar = (mb + mt * 16 + a_row) * ROWB + kbyte + a_kh;
            ldmx4(ah[mt], sAh + ar);
            ldmx4(al[mt], sAl + ar);
        }
#pragma unroll
        for (int q = 0; q < 4; q++) {
            uint32_t br = (nb + q * 16 + b_row) * ROWB + kbyte + b_kh;
            ldmx4(bh[q], sBh + br);
            ldmx4(bl[q], sBl + br);
        }
#pragma unroll
        for (int mt = 0; mt < 2; mt++) {
#pragma unroll
            for (int nf = 0; nf < 8; nf++) {
                uint32_t h0 = bh[nf >> 1][(nf & 1) * 2], h1 = bh[nf >> 1][(nf & 1) * 2 + 1];
                uint32_t l0 = bl[nf >> 1][(nf & 1) * 2], l1 = bl[nf >> 1][(nf & 1) * 2 + 1];
                mma16816(acc[mt][nf], ah[mt], h0, h1);
                mma16816(acc[mt][nf], ah[mt], l0, l1);
                mma16816(acc[mt][nf], al[mt], h0, h1);
            }
        }
    }

    // ---- epilogue ----
    // thread holds c[row = m0+mb+mt*16+(pair*8)+lane/4][col = nb+nf*8+2*(lane%4)+{0,1}]
    const int rbase = m0 + mb + (lane >> 2);
    const int cbase = nb + 2 * (lane & 3);
#pragma unroll
    for (int mt = 0; mt < 2; mt++) {
#pragma unroll
        for (int pair = 0; pair < 2; pair++) {
            int m = rbase + mt * 16 + pair * 8;
            if (m >= N_NODESC) continue;
            if (t < 16) {
                __nv_bfloat16* dp = g_projb + ((size_t)t * N_NODESC + m) * DIMC;
#pragma unroll
                for (int nf = 0; nf < 8; nf++) {
                    float v0 = acc[mt][nf][pair * 2 + 0];
                    float v1 = acc[mt][nf][pair * 2 + 1];
                    uint32_t pk;
                    asm("cvt.rn.satfinite.bf16x2.f32 %0, %1, %2;" : "=r"(pk) : "f"(v1), "f"(v0));
                    *(uint32_t*)(dp + cbase + nf * 8) = pk;
                }
            } else {
                float* dp = g_q + (size_t)m * DIMC;
#pragma unroll
                for (int nf = 0; nf < 8; nf++) {
                    *(float2*)(dp + cbase + nf * 8) =
                        make_float2(acc[mt][nf][pair * 2], acc[mt][nf][pair * 2 + 1]);
                }
            }
        }
    }
}

// ---------------- per-edge attention score ----------------
__global__ void k_score(const int* __restrict__ src, const int* __restrict__ dst,
                        const float* __restrict__ rel_att, const float* __restrict__ b_a) {
    int e = blockIdx.x * 8 + threadIdx.y;
    int lane = threadIdx.x;
    int s = __ldg(&src[e]);
    int d = __ldg(&dst[e]);
    float2 qd = *(const float2*)&g_q[(size_t)d * DIMC + lane * 2];
    float2 qs = *(const float2*)&g_q[(size_t)s * DIMC + A_DIMC + lane * 2];
    float2 ba = *(const float2*)&b_a[lane * 2];
    float2 ra = *(const float2*)&rel_att[lane * 2];
    float x0 = qd.x + qs.x + ba.x;
    x0 = x0 > 0.f ? x0 : 0.01f * x0;
    float x1 = qd.y + qs.y + ba.y;
    x1 = x1 > 0.f ? x1 : 0.01f * x1;
    float p = ra.x * x0 + ra.y * x1;
#pragma unroll
    for (int o = 16; o > 0; o >>= 1) p += __shfl_xor_sync(0xffffffffu, p, o);
    if (lane == 0) {
        float ex = expf(p);
        g_ex[e] = ex;
        atomicAdd(&g_denom[d], ex);
    }
}

// ---------------- per-edge message (bf16 proj table) ----------------
__global__ void k_msg(const float* __restrict__ h, const int* __restrict__ src,
                      const int* __restrict__ dst, const int* __restrict__ etype) {
    int e = blockIdx.x * 8 + threadIdx.y;
    int lane = threadIdx.x;
    int s = __ldg(&src[e]);
    int d = __ldg(&dst[e]);
    int r = __ldg(&etype[e]);
    float attn = __fdividef(g_ex[e], g_denom[d]);
    uint2 pdw = *(const uint2*)(g_projb + ((size_t)r * N_NODESC + d) * DIMC + lane * 4);
    uint2 psw = *(const uint2*)(g_projb + ((size_t)(8 + r) * N_NODESC + s) * DIMC + lane * 4);
    float2 pd0 = __bfloat1622float2(*(__nv_bfloat162*)&pdw.x);
    float2 pd1 = __bfloat1622float2(*(__nv_bfloat162*)&pdw.y);
    float2 ps0 = __bfloat1622float2(*(__nv_bfloat162*)&psw.x);
    float2 ps1 = __bfloat1622float2(*(__nv_bfloat162*)&psw.y);
    float4 hs = *(const float4*)&h[(size_t)s * DIMC + lane * 4];
    float g0 = 1.0f / (1.0f + expf(-(pd0.x + ps0.x)));
    float g1 = 1.0f / (1.0f + expf(-(pd0.y + ps0.y)));
    float g2 = 1.0f / (1.0f + expf(-(pd1.x + ps1.x)));
    float g3 = 1.0f / (1.0f + expf(-(pd1.y + ps1.y)));
    float* o = &g_hN[(size_t)d * DIMC + lane * 4];
    atomicAdd(o + 0, hs.x * attn * g0);
    atomicAdd(o + 1, hs.y * attn * g1);
    atomicAdd(o + 2, hs.z * attn * g2);
    atomicAdd(o + 3, hs.w * attn * g3);
}

// ---------------- f32x2 packed-FMA helpers for final GEMM ----------------
__device__ __forceinline__ unsigned long long pack2(float x) {
    unsigned long long r;
    asm("mov.b64 %0, {%1, %1};" : "=l"(r) : "f"(x));
    return r;
}
__device__ __forceinline__ void ffma2(unsigned long long& acc, unsigned long long a,
                                      unsigned long long b) {
    asm("fma.rn.f32x2 %0, %1, %2, %0;" : "+l"(acc) : "l"(a), "l"(b));
}
__device__ __forceinline__ float2 unpack2(unsigned long long v) {
    float2 r;
    asm("mov.b64 {%0, %1}, %2;" : "=f"(r.x), "=f"(r.y) : "l"(v));
    return r;
}

// ---------------- final: out = leaky([h ; h_N] @ W_lin^T + b_lin) ----------------
__global__ __launch_bounds__(256) void k_final(const float* __restrict__ h,
                                               const float* __restrict__ b_lin,
                                               float* __restrict__ out) {
    __shared__ float As[16][132];
    __shared__ float Bs[16][128];

    const int tid = threadIdx.x;
    const int m0 = blockIdx.x * 128;
    const int tr = tid >> 4;
    const int tc = tid & 15;
    const int a_row = tid >> 2;
    const int a_col = (tid & 3) << 2;
    const int b_row = tid >> 5;
    const int b_col = (tid & 31) << 2;

    unsigned long long acc[8][4];
#pragma unroll
    for (int i = 0; i < 8; i++)
#pragma unroll
        for (int j = 0; j < 4; j++) acc[i][j] = 0ull;

    for (int k0 = 0; k0 < 2 * DIMC; k0 += 16) {
        const float* Asrc = (k0 < DIMC) ? (h + k0) : (g_hN + (k0 - DIMC));
#pragma unroll
        for (int half = 0; half < 2; half++) {
            int m = a_row + half * 64;
            float4 v = make_float4(0.f, 0.f, 0.f, 0.f);
            if (m0 + m < N_NODESC)
                v = *(const float4*)(Asrc + (size_t)(m0 + m) * DIMC + a_col);
            As[a_col + 0][m] = v.x;
            As[a_col + 1][m] = v.y;
            As[a_col + 2][m] = v.z;
            As[a_col + 3][m] = v.w;
        }
#pragma unroll
        for (int half = 0; half < 2; half++) {
            int kk = b_row + half * 8;
            *(float4*)&Bs[kk][b_col] =
                *(const float4*)(g_WlT + (size_t)(k0 + kk) * DIMC + b_col);
        }
        __syncthreads();

#pragma unroll
        for (int k = 0; k < 16; k++) {
            float4 a0 = *(const float4*)&As[k][tr * 8];
            float4 a1 = *(const float4*)&As[k][tr * 8 + 4];
            unsigned long long ap[8];
            ap[0] = pack2(a0.x); ap[1] = pack2(a0.y); ap[2] = pack2(a0.z); ap[3] = pack2(a0.w);
            ap[4] = pack2(a1.x); ap[5] = pack2(a1.y); ap[6] = pack2(a1.z); ap[7] = pack2(a1.w);
            ulonglong2 bq0 = *(const ulonglong2*)&Bs[k][tc * 8];
            ulonglong2 bq1 = *(const ulonglong2*)&Bs[k][tc * 8 + 4];
            unsigned long long bp[4] = {bq0.x, bq0.y, bq1.x, bq1.y};
#pragma unroll
            for (int i = 0; i < 8; i++)
#pragma unroll
                for (int j = 0; j < 4; j++) ffma2(acc[i][j], ap[i], bp[j]);
        }
        __syncthreads();
    }

#pragma unroll
    for (int i = 0; i < 8; i++) {
        int m = m0 + tr * 8 + i;
        if (m < N_NODESC) {
            float* cp = out + (size_t)m * DIMC + tc * 8;
#pragma unroll
            for (int j = 0; j < 4; j++) {
                float2 p = unpack2(acc[i][j]);
                float2 bl = *(const float2*)&b_lin[tc * 8 + j * 2];
                float v0 = p.x + bl.x;
                float v1 = p.y + bl.y;
                v0 = v0 > 0.f ? v0 : 0.01f * v0;
                v1 = v1 > 0.f ? v1 : 0.01f * v1;
                *(float2*)(cp + j * 2) = make_float2(v0, v1);
            }
        }
    }
}

// ---------------- launch ----------------
extern "C" void kernel_launch(void* const* d_in, const int* in_sizes, int n_in,
                              void* d_out, int out_size) {
    const float* h      = (const float*)d_in[0];
    const float* rel    = (const float*)d_in[1];
    const float* relatt = (const float*)d_in[2];
    const float* W_a    = (const float*)d_in[3];
    const float* b_a    = (const float*)d_in[4];
    const float* W_lin  = (const float*)d_in[5];
    const float* b_lin  = (const float*)d_in[6];
    const int* src   = (const int*)d_in[7];
    const int* dst   = (const int*)d_in[8];
    const int* etype = (const int*)d_in[9];
    float* out = (float*)d_out;

    cudaFuncSetAttribute(k_tgemm, cudaFuncAttributeMaxDynamicSharedMemorySize, SM_TOTAL);

    k_zero<<<(N_NODESC * DIMC + 1023) / 1024, 1024>>>();
    k_cvtA<<<(N_NODESC * DIMC + 255) / 256, 256>>>(h);
    k_prepB<<<(TCNT * DIMC * DIMC + 255) / 256, 256>>>(rel, W_a, W_lin);

    dim3 gg(MBLKS, TCNT);
    k_tgemm<<<gg, 256, SM_TOTAL>>>();

    dim3 be(32, 8);
    k_score<<<N_EDGESC / 8, be>>>(src, dst, relatt, b_a);
    k_msg<<<N_EDGESC / 8, be>>>(h, src, dst, etype);

    k_final<<<(N_NODESC + 127) / 128, 256>>>(h, b_lin, out);
}